// round 15
// baseline (speedup 1.0000x reference)
#include <cuda_runtime.h>

// Laplacian_Forward_Model — column-per-lane, smem-free, barrier-free,
// packed f32x2 math (rows y and y+16 per lane processed simultaneously).
// One warp per image; lane = column. No STS/LDS/BAR anywhere.
//
// input (B,1,32,32) f32; weight (n_mult,9); weight_factor (n_mult,1);
// output (n_mult,B,1,32,32) f32.

#define TPB 128
typedef unsigned long long u64;

// Order-preserving float<->int map (self-inverse, monotone for finite values).
__device__ __forceinline__ int f2ord(float x) {
    int b = __float_as_int(x);
    return b ^ ((b >> 31) & 0x7FFFFFFF);
}
__device__ __forceinline__ float ord2f(int k) {
    return __int_as_float(k ^ ((k >> 31) & 0x7FFFFFFF));
}
__device__ __forceinline__ float fma_sat(float a, float b, float c) {
    float r;
    asm("fma.rn.sat.f32 %0, %1, %2, %3;" : "=f"(r) : "f"(a), "f"(b), "f"(c));
    return r;
}
__device__ __forceinline__ void stg_cs(float* p, float v) {
    asm volatile("st.global.cs.f32 [%0], %1;" :: "l"(p), "f"(v) : "memory");
}
// ---- packed f32x2 helpers (Blackwell FFMA2 path) ----
__device__ __forceinline__ u64 pack2(float lo, float hi) {
    u64 r; asm("mov.b64 %0, {%1, %2};" : "=l"(r) : "f"(lo), "f"(hi)); return r;
}
__device__ __forceinline__ void unpack2(u64 v, float& lo, float& hi) {
    asm("mov.b64 {%0, %1}, %2;" : "=f"(lo), "=f"(hi) : "l"(v));
}
__device__ __forceinline__ u64 fma2(u64 a, u64 b, u64 c) {
    u64 d; asm("fma.rn.f32x2 %0, %1, %2, %3;" : "=l"(d) : "l"(a), "l"(b), "l"(c)); return d;
}
__device__ __forceinline__ u64 add2(u64 a, u64 b) {
    u64 d; asm("add.rn.f32x2 %0, %1, %2;" : "=l"(d) : "l"(a), "l"(b)); return d;
}
__device__ __forceinline__ u64 mul2(u64 a, u64 b) {
    u64 d; asm("mul.rn.f32x2 %0, %1, %2;" : "=l"(d) : "l"(a), "l"(b)); return d;
}

__global__ __launch_bounds__(TPB)
void lap_fwd_kernel(const float* __restrict__ in,
                    const float* __restrict__ weight,
                    const float* __restrict__ wfac,
                    float* __restrict__ out,
                    int B)
{
    const int tid  = threadIdx.x;
    const int wid  = tid >> 5;
    const int lane = tid & 31;
    const int b    = blockIdx.x * 4 + wid;   // image index (one per warp)
    const int ii   = blockIdx.y;
    const unsigned FULL = 0xffffffffu;

    if (b >= B) return;               // warp-uniform

    // ---- clamped 3x3 kernel, broadcast-packed (warp-uniform) ----
    float wfv = fminf(fmaxf(wfac[ii], 1.001f), 254.999f);
    u64 kp[9];
#pragma unroll
    for (int j = 0; j < 9; ++j) {
        float w = weight[ii * 9 + j];
        float kj = fminf(fmaxf(w, -0.999f), 0.999f) * wfv;
        kp[j] = pack2(kj, kj);
    }

    const float* src = in + (size_t)b * 1024 + lane;   // this lane's column

    // ---- pass 1: packed streaming 3x3 conv; lane pair = rows (i, i+16) ----
    // cv2[i] = (conv[row i], conv[row i+16])
    u64 cv2[16];
    u64 pp2  = 0ull;    // (h0(y-1)+h1(y)) per half
    u64 h0p2 = 0ull;    // h0 of previous row per half
    float h2_16 = 0.f;  // h2(row 16), needed to finish cv[15]
#pragma unroll
    for (int i = 0; i < 16; ++i) {
        float xlo = src[i * 32];
        float xhi = src[(i + 16) * 32];
        float Llo = __shfl_up_sync(FULL, xlo, 1);
        float Lhi = __shfl_up_sync(FULL, xhi, 1);
        float Rlo = __shfl_down_sync(FULL, xlo, 1);
        float Rhi = __shfl_down_sync(FULL, xhi, 1);
        if (lane == 0)  { Llo = 0.f; Lhi = 0.f; }
        if (lane == 31) { Rlo = 0.f; Rhi = 0.f; }
        u64 x2 = pack2(xlo, xhi);
        u64 L2 = pack2(Llo, Lhi);
        u64 R2 = pack2(Rlo, Rhi);
        u64 h0 = fma2(kp[0], L2, fma2(kp[1], x2, mul2(kp[2], R2)));
        u64 h1 = fma2(kp[3], L2, fma2(kp[4], x2, mul2(kp[5], R2)));
        u64 h2 = fma2(kp[6], L2, fma2(kp[7], x2, mul2(kp[8], R2)));
        if (i > 0) {
            cv2[i - 1] = add2(pp2, h2);
        } else {
            float t0, t1; unpack2(h2, t0, t1);
            h2_16 = t1;                          // h2(row 16)
        }
        pp2  = add2(h0p2, h1);
        h0p2 = h0;
    }
    // end patches across the half boundary
    {
        float pp_lo, pp_hi;   unpack2(pp2,  pp_lo,  pp_hi);
        float h0_15, h0_31;   unpack2(h0p2, h0_15,  h0_31);
        cv2[15] = pack2(pp_lo + h2_16, pp_hi);   // cv[15], cv[31]
        float a, h; unpack2(cv2[0], a, h);
        cv2[0] = pack2(a, h + h0_15);            // cv[16] += h0(15)
    }

    // ---- reduction 1: min/max of conv over image ----
    float mn, mx;
    {
        float a, h; unpack2(cv2[0], a, h);
        mn = fminf(a, h); mx = fmaxf(a, h);
#pragma unroll
        for (int j = 1; j < 16; ++j) {
            unpack2(cv2[j], a, h);
            mn = fminf(mn, fminf(a, h));
            mx = fmaxf(mx, fmaxf(a, h));
        }
    }
    float cmin = ord2f(__reduce_min_sync(FULL, f2ord(mn)));
    float cmax = ord2f(__reduce_max_sync(FULL, f2ord(mx)));

    // ---- pass 2: packed sharpen, x reloaded from gmem (L1-resident) ----
    float s1 = 255.0f / fmaxf(cmax - cmin, 1e-6f);   // warp-uniform
    u64 s12  = pack2(s1, s1);
    u64 ncm2 = pack2(-cmin, -cmin);
#pragma unroll
    for (int i = 0; i < 16; ++i) {
        float xlo = __ldg(src + i * 32);
        float xhi = __ldg(src + (i + 16) * 32);
        cv2[i] = fma2(add2(cv2[i], ncm2), s12, pack2(xlo, xhi));
    }

    // ---- reduction 2: min/max of sharpened ----
    {
        float a, h; unpack2(cv2[0], a, h);
        mn = fminf(a, h); mx = fmaxf(a, h);
#pragma unroll
        for (int j = 1; j < 16; ++j) {
            unpack2(cv2[j], a, h);
            mn = fminf(mn, fminf(a, h));
            mx = fmaxf(mx, fmaxf(a, h));
        }
    }
    float smin = ord2f(__reduce_min_sync(FULL, f2ord(mn)));
    float smax = ord2f(__reduce_max_sync(FULL, f2ord(mx)));

    // ---- pass 3: u = sat((sh-smin)*invd); out = floor(255*u) ----
    float invd = 1.0f / fminf(fmaxf(smax - smin, 1e-6f), 255.0f);
    float d2   = -smin * invd;
    float* dst = out + ((size_t)ii * B + b) * 1024 + lane;
#pragma unroll
    for (int i = 0; i < 16; ++i) {
        float lo, hi; unpack2(cv2[i], lo, hi);
        float ulo = fma_sat(lo, invd, d2);
        float uhi = fma_sat(hi, invd, d2);
        stg_cs(dst + i * 32,        floorf(ulo * 255.0f));
        stg_cs(dst + (i + 16) * 32, floorf(uhi * 255.0f));
    }
}

extern "C" void kernel_launch(void* const* d_in, const int* in_sizes, int n_in,
                              void* d_out, int out_size)
{
    const float* in  = (const float*)d_in[0];
    const float* w   = (const float*)d_in[1];
    const float* wf  = (const float*)d_in[2];
    float* out       = (float*)d_out;

    int B      = in_sizes[0] / 1024;
    int n_mult = in_sizes[1] / 9;

    dim3 grid((B + 3) / 4, n_mult);
    lap_fwd_kernel<<<grid, TPB>>>(in, w, wf, out, B);
}